// round 6
// baseline (speedup 1.0000x reference)
#include <cuda_runtime.h>
#include <cuda_bf16.h>
#include <math.h>

#define BZ 32
#define SZ 128
#define HZ 768
#define MM 8
#define MH_ 6
#define KK 4

__constant__ float c_inv[8] = {1.f, 1.f/2.f, 1.f/3.f, 1.f/4.f, 1.f/5.f, 1.f/6.f, 1.f/7.f, 1.f/8.f};

#define CE(x, y) { unsigned long long _a = (x), _b = (y); (x) = _a > _b ? _a : _b; (y) = _a > _b ? _b : _a; }

__device__ float g_dots[BZ * 2 * SZ];                 // [B][2][S]: 0=target(wt),1=holder(wh)
__device__ unsigned long long g_cand[BZ * 2 * 4 * 4]; // [B][type][quarter][4]

// out layout (floats): implicit[0,512) explicit[512,2560) hs[2560,35328) ts[35328,68096)

// ---------------------------------------------------------------------------
// K1: per-row wh/wt dots. grid (BZ,4)=128 blocks, 256 thr, 4 rows/warp.
// ---------------------------------------------------------------------------
__global__ __launch_bounds__(256, 1) void k_dots(
    const float* __restrict__ emb,
    const float* __restrict__ wh,
    const float* __restrict__ wt)
{
    const int b = blockIdx.x;
    const int tid = threadIdx.x;
    const int warp = tid >> 5, lane = tid & 31;

    float4 wh4[6], wt4[6];
#pragma unroll
    for (int i = 0; i < 6; i++) {
        wh4[i] = ((const float4*)wh)[lane + 32 * i];
        wt4[i] = ((const float4*)wt)[lane + 32 * i];
    }
    const int r0 = blockIdx.y * 32 + warp * 4;
    const float* eb = emb + ((size_t)b * SZ + r0) * HZ;

    float4 v[4][6];
#pragma unroll
    for (int r = 0; r < 4; r++) {
        const float4* rp = (const float4*)(eb + (size_t)r * HZ);
#pragma unroll
        for (int i = 0; i < 6; i++) v[r][i] = rp[lane + 32 * i];
    }
#pragma unroll
    for (int r = 0; r < 4; r++) {
        float ah = 0.f, at = 0.f;
#pragma unroll
        for (int i = 0; i < 6; i++) {
            ah += v[r][i].x * wh4[i].x + v[r][i].y * wh4[i].y
                + v[r][i].z * wh4[i].z + v[r][i].w * wh4[i].w;
            at += v[r][i].x * wt4[i].x + v[r][i].y * wt4[i].y
                + v[r][i].z * wt4[i].z + v[r][i].w * wt4[i].w;
        }
#pragma unroll
        for (int off = 16; off; off >>= 1) {
            ah += __shfl_xor_sync(0xFFFFFFFFu, ah, off);
            at += __shfl_xor_sync(0xFFFFFFFFu, at, off);
        }
        if (lane == 0) {
            g_dots[b * 2 * SZ + (r0 + r)]      = at;
            g_dots[b * 2 * SZ + SZ + (r0 + r)] = ah;
        }
    }
}

// ---------------------------------------------------------------------------
// K2: scores + hs/ts + per-quarter top-4 candidates.
// grid (BZ, 4) = 128 blocks, 256 thr. Each block owns 256 span indices.
// ---------------------------------------------------------------------------
__global__ __launch_bounds__(256, 1) void k_scores(
    const int* __restrict__ mask,
    const float* __restrict__ bh_,
    const float* __restrict__ bt_,
    float* __restrict__ out)
{
    __shared__ float pref[2][SZ + 1];
    __shared__ float sc[2][256];
    __shared__ unsigned long long cand[2][16];
    __shared__ int s_len;

    const int b = blockIdx.x, q = blockIdx.y;
    const int tid = threadIdx.x;
    const int warp = tid >> 5, lane = tid & 31;

    if (tid < 2) pref[tid][0] = 0.f;
    if (tid == 0) s_len = 0;
    pref[tid >> 7][(tid & 127) + 1] = g_dots[b * 2 * SZ + tid];
    __syncthreads();

    if (warp < 2) {
        // prefix scan over S for channel `warp`
        const int c = warp;
        float v0 = pref[c][lane * 4 + 1];
        float v1 = pref[c][lane * 4 + 2];
        float v2 = pref[c][lane * 4 + 3];
        float v3 = pref[c][lane * 4 + 4];
        v1 += v0; v2 += v1; v3 += v2;
        float tot = v3, x = tot;
#pragma unroll
        for (int off = 1; off < 32; off <<= 1) {
            float y = __shfl_up_sync(0xFFFFFFFFu, x, off);
            if (lane >= off) x += y;
        }
        float excl = x - tot;
        pref[c][lane * 4 + 1] = v0 + excl;
        pref[c][lane * 4 + 2] = v1 + excl;
        pref[c][lane * 4 + 3] = v2 + excl;
        pref[c][lane * 4 + 4] = v3 + excl;
    } else if (warp >= 4) {
        // mask length (warps 4-7 cover all 128 positions)
        int v = mask[b * SZ + (tid - 128)];
#pragma unroll
        for (int off = 16; off; off >>= 1) v += __shfl_xor_sync(0xFFFFFFFFu, v, off);
        if (lane == 0) atomicAdd(&s_len, v);
    }
    __syncthreads();

    // scores, 1 span per thread
    {
        const int len = s_len;
        const int gidx = q * 256 + tid;
        const int m = gidx >> 7, s = gidx & 127;
        int e = s + m + 1; if (e > SZ) e = SZ;
        float invw = c_inv[m];
        bool tv = (s + m) < len;
        bool hv = tv && (m < MH_);
        float dt = (pref[0][e] - pref[0][s]) * invw;
        float dh = (pref[1][e] - pref[1][s]) * invw;
        float vt = tv ? 1.f / (1.f + __expf(-(dt + bt_[0]))) : -1.f;
        float vh = hv ? 1.f / (1.f + __expf(-(dh + bh_[0]))) : -1.f;
        sc[0][tid] = vt; sc[1][tid] = vh;
        out[35328 + (size_t)b * (MM * SZ) + gidx] = vt;
        out[2560  + (size_t)b * (MM * SZ) + gidx] = vh;
    }
    __syncthreads();

    // per-warp top-4 over its 64-span window (t: warps 0-3, h: warps 4-7)
    {
        const int type = warp >> 2;
        const int wq = warp & 3;
        const int l0 = wq * 64 + lane, l1 = l0 + 32;
        unsigned long long k0, k1, k2 = 0ull, k3 = 0ull;
        {
            unsigned u0 = __float_as_uint(sc[type][l0]);
            unsigned u1 = __float_as_uint(sc[type][l1]);
            u0 = (u0 & 0x80000000u) ? ~u0 : (u0 | 0x80000000u);
            u1 = (u1 & 0x80000000u) ? ~u1 : (u1 | 0x80000000u);
            k0 = ((unsigned long long)u0 << 32) | (unsigned)(0xFFFFFFFFu - (q * 256 + l0));
            k1 = ((unsigned long long)u1 << 32) | (unsigned)(0xFFFFFFFFu - (q * 256 + l1));
            CE(k0, k1);
        }
#pragma unroll
        for (int off = 16; off; off >>= 1) {
            unsigned long long o0 = __shfl_xor_sync(0xFFFFFFFFu, k0, off);
            unsigned long long o1 = __shfl_xor_sync(0xFFFFFFFFu, k1, off);
            unsigned long long o2 = __shfl_xor_sync(0xFFFFFFFFu, k2, off);
            unsigned long long o3 = __shfl_xor_sync(0xFFFFFFFFu, k3, off);
            unsigned long long c0 = k0 > o3 ? k0 : o3;
            unsigned long long c1 = k1 > o2 ? k1 : o2;
            unsigned long long c2 = k2 > o1 ? k2 : o1;
            unsigned long long c3 = k3 > o0 ? k3 : o0;
            CE(c0, c2); CE(c1, c3);
            CE(c0, c1); CE(c2, c3);
            k0 = c0; k1 = c1; k2 = c2; k3 = c3;
        }
        if (lane == 0) {
            cand[type][wq * 4 + 0] = k0;
            cand[type][wq * 4 + 1] = k1;
            cand[type][wq * 4 + 2] = k2;
            cand[type][wq * 4 + 3] = k3;
        }
    }
    __syncthreads();

    // block-level top-4 of 16 candidates -> global (warps 0 and 4)
    if (warp == 0 || warp == 4) {
        const int type = warp >> 2;
        unsigned long long key = (lane < 16) ? cand[type][lane] : 0ull;
#pragma unroll
        for (int k = 0; k < KK; k++) {
            unsigned long long red = key;
#pragma unroll
            for (int off = 16; off; off >>= 1) {
                unsigned long long o = __shfl_xor_sync(0xFFFFFFFFu, red, off);
                red = o > red ? o : red;
            }
            if (key == red) key = 0ull;
            if (lane == 0)
                g_cand[((b * 2 + type) * 4 + q) * 4 + k] = red;
        }
    }
}

// ---------------------------------------------------------------------------
// K3: merge candidates, selected-span rep dots, logits. grid BZ, 512 thr.
// ---------------------------------------------------------------------------
__global__ __launch_bounds__(512, 1) void k_final(
    const float* __restrict__ emb,
    const float* __restrict__ wi,
    const float* __restrict__ bi,
    const float* __restrict__ we,
    const float* __restrict__ be,
    float* __restrict__ out)
{
    __shared__ __align__(16) float swi[HZ * 4];        // 12 KB
    __shared__ __align__(16) float swe[2 * HZ * 4];    // 24 KB
    __shared__ float topv[2][KK];
    __shared__ int   topi[2][KK];
    __shared__ float partial[16][8];
    __shared__ float sbias[8];                          // 0-3: bi, 4-7: be

    const int b = blockIdx.x;
    const int tid = threadIdx.x;
    const int warp = tid >> 5, lane = tid & 31;
    const float* eb = emb + (size_t)b * SZ * HZ;

    // weight prefetch burst (overlaps the candidate merge below)
    {
        float4* swi4 = (float4*)swi;
        float4* swe4 = (float4*)swe;
        const float4* wi4 = (const float4*)wi;
        const float4* we4 = (const float4*)we;
#pragma unroll
        for (int i = 0; i < 5; i++) {
            int j = tid + 512 * i;
            if (j < 768)       swi4[j] = wi4[j];
            else if (j < 2304) swe4[j - 768] = we4[j - 768];
        }
        if (tid < 4)            sbias[tid]     = bi[tid];
        else if (tid < 8)       sbias[tid]     = be[tid - 4];
    }

    // candidate merge: warp 0 -> targets, warp 1 -> holders
    if (warp < 2) {
        const int type = warp;
        unsigned long long key = (lane < 16) ? g_cand[(b * 2 + type) * 16 + lane] : 0ull;
#pragma unroll
        for (int k = 0; k < KK; k++) {
            unsigned long long red = key;
#pragma unroll
            for (int off = 16; off; off >>= 1) {
                unsigned long long o = __shfl_xor_sync(0xFFFFFFFFu, red, off);
                red = o > red ? o : red;
            }
            if (key == red) key = 0ull;
            if (lane == 0) {
                unsigned hi = (unsigned)(red >> 32);
                unsigned lo = (unsigned)red;
                float v = (hi & 0x80000000u) ? __uint_as_float(hi ^ 0x80000000u)
                                             : __uint_as_float(~hi);
                topv[type][k] = v;
                topi[type][k] = (int)(0xFFFFFFFFu - lo);
            }
        }
    }
    __syncthreads();

    // rep dots: 2 warps per span (16 warps), 3 float4-chunks per warp
    {
        const int type = warp >> 3;          // 0=target, 1=holder
        const int span = (warp >> 1) & 3;
        const int half = warp & 1;
        const int idx = topi[type][span];
        const bool valid = topv[type][span] > 0.f;
        const int m = idx >> 7, s = idx & 127;
        const float invw = c_inv[m];

        float4 sum0 = make_float4(0.f,0.f,0.f,0.f);
        float4 sum1 = sum0, sum2 = sum0;
        if (valid) {
            const int c0i = lane + 96 * half;
#pragma unroll
            for (int r = 0; r < 8; r++) {
                if (r <= m) {
                    const float4* rp = (const float4*)(eb + (size_t)(s + r) * HZ);
                    float4 a = rp[c0i], bb = rp[c0i + 32], cc = rp[c0i + 64];
                    sum0.x += a.x;  sum0.y += a.y;  sum0.z += a.z;  sum0.w += a.w;
                    sum1.x += bb.x; sum1.y += bb.y; sum1.z += bb.z; sum1.w += bb.w;
                    sum2.x += cc.x; sum2.y += cc.y; sum2.z += cc.z; sum2.w += cc.w;
                }
            }
        }
        float acc[8] = {0.f,0.f,0.f,0.f,0.f,0.f,0.f,0.f};
        if (valid) {
            const float4* swi4 = (const float4*)swi;
            const float4* swe4 = (const float4*)swe;
            float4 sums[3] = {sum0, sum1, sum2};
#pragma unroll
            for (int c = 0; c < 3; c++) {
                int h4 = lane + 96 * half + 32 * c;
                float sv[4] = {sums[c].x * invw, sums[c].y * invw,
                               sums[c].z * invw, sums[c].w * invw};
#pragma unroll
                for (int j = 0; j < 4; j++) {
                    int f = 4 * h4 + j;
                    if (type == 0) {
                        float4 wv = swi4[f];
                        acc[0] += sv[j] * wv.x; acc[1] += sv[j] * wv.y;
                        acc[2] += sv[j] * wv.z; acc[3] += sv[j] * wv.w;
                        float4 ev = swe4[HZ + f];
                        acc[4] += sv[j] * ev.x; acc[5] += sv[j] * ev.y;
                        acc[6] += sv[j] * ev.z; acc[7] += sv[j] * ev.w;
                    } else {
                        float4 ev = swe4[f];
                        acc[0] += sv[j] * ev.x; acc[1] += sv[j] * ev.y;
                        acc[2] += sv[j] * ev.z; acc[3] += sv[j] * ev.w;
                    }
                }
            }
        }
#pragma unroll
        for (int j = 0; j < 8; j++)
#pragma unroll
            for (int off = 16; off; off >>= 1)
                acc[j] += __shfl_xor_sync(0xFFFFFFFFu, acc[j], off);
        if (lane == 0) {
#pragma unroll
            for (int j = 0; j < 8; j++) partial[warp][j] = acc[j];
        }
    }
    __syncthreads();

    // logits
    if (tid < 64) {
        int k = tid >> 4, i = (tid >> 2) & 3, j = tid & 3;
        bool pv = (topv[1][k] > 0.f) && (topv[0][i] > 0.f);
        float val = sbias[4 + j];
        if (pv) val += partial[8 + 2*k][j] + partial[9 + 2*k][j]
                     + partial[2*i][4 + j] + partial[2*i + 1][4 + j];
        out[512 + (size_t)b * 64 + tid] = val;
    } else if (tid < 80) {
        int t2 = tid - 64;
        int i = t2 >> 2, j = t2 & 3;
        float val = sbias[j];
        if (topv[0][i] > 0.f) val += partial[2*i][j] + partial[2*i + 1][j];
        out[(size_t)b * 16 + t2] = val;
    }
}

extern "C" void kernel_launch(void* const* d_in, const int* in_sizes, int n_in,
                              void* d_out, int out_size)
{
    const float* emb = (const float*)d_in[0];
    const int*   msk = (const int*)d_in[1];
    const float* wh  = (const float*)d_in[2];
    const float* bh  = (const float*)d_in[3];
    const float* wt  = (const float*)d_in[4];
    const float* bt  = (const float*)d_in[5];
    const float* wi  = (const float*)d_in[6];
    const float* bi  = (const float*)d_in[7];
    const float* we  = (const float*)d_in[8];
    const float* be  = (const float*)d_in[9];
    float* out = (float*)d_out;

    dim3 g1(BZ, 4, 1);
    k_dots<<<g1, 256>>>(emb, wh, wt);
    k_scores<<<g1, 256>>>(msk, bh, bt, out);
    k_final<<<BZ, 512>>>(emb, wi, bi, we, be, out);
}

// round 7
// speedup vs baseline: 1.3879x; 1.3879x over previous
#include <cuda_runtime.h>
#include <cuda_bf16.h>
#include <math.h>

#define BZ 32
#define SZ 128
#define HZ 768
#define MH_ 6
#define KK 4

__constant__ float c_inv[8] = {1.f, 1.f/2.f, 1.f/3.f, 1.f/4.f, 1.f/5.f, 1.f/6.f, 1.f/7.f, 1.f/8.f};

__device__ float g_dots[BZ * 2 * SZ];       // [B][2][S]: 0=target(wt),1=holder(wh)
__device__ unsigned int g_tick[BZ];         // zero-init; elected block resets

#define CE(x, y) { unsigned long long _a = (x), _b = (y); (x) = _a > _b ? _a : _b; (y) = _a > _b ? _b : _a; }

// out layout (floats): implicit[0,512) explicit[512,2560) hs[2560,35328) ts[35328,68096)

__global__ __launch_bounds__(256, 1) void k_all(
    const float* __restrict__ emb,
    const int* __restrict__ mask,
    const float* __restrict__ wh,
    const float* __restrict__ bh_,
    const float* __restrict__ wt,
    const float* __restrict__ bt_,
    const float* __restrict__ wi,
    const float* __restrict__ bi,
    const float* __restrict__ we,
    const float* __restrict__ be,
    float* __restrict__ out)
{
    __shared__ float pref[2][SZ + 1];
    __shared__ unsigned long long candT[32];
    __shared__ unsigned long long candH[32];
    __shared__ float topv[2][KK];
    __shared__ int   topi[2][KK];
    __shared__ float partial[8][8];
    __shared__ float sbias[8];     // 0-3: bi, 4-7: be
    __shared__ float s_bh, s_bt;
    __shared__ int s_flag, s_len;

    const int b = blockIdx.x, q = blockIdx.y;
    const int tid = threadIdx.x;
    const int warp = tid >> 5, lane = tid & 31;
    const float* eb = emb + (size_t)b * SZ * HZ;

    if (tid == 0) s_flag = 0;
    __syncthreads();                                   // B1

    // ================= Phase A: row dots (all 128 blocks) =================
    {
        float4 wh4[6], wt4[6];
#pragma unroll
        for (int i = 0; i < 6; i++) {
            wh4[i] = ((const float4*)wh)[lane + 32 * i];
            wt4[i] = ((const float4*)wt)[lane + 32 * i];
        }
        const int r0 = q * 32 + warp * 4;
        float4 v[4][6];
#pragma unroll
        for (int r = 0; r < 4; r++) {
            const float4* rp = (const float4*)(eb + (size_t)(r0 + r) * HZ);
#pragma unroll
            for (int i = 0; i < 6; i++) v[r][i] = rp[lane + 32 * i];
        }
        float ah[4], at[4];
#pragma unroll
        for (int r = 0; r < 4; r++) {
            float a = 0.f, t = 0.f;
#pragma unroll
            for (int i = 0; i < 6; i++) {
                a += v[r][i].x * wh4[i].x + v[r][i].y * wh4[i].y
                   + v[r][i].z * wh4[i].z + v[r][i].w * wh4[i].w;
                t += v[r][i].x * wt4[i].x + v[r][i].y * wt4[i].y
                   + v[r][i].z * wt4[i].z + v[r][i].w * wt4[i].w;
            }
            ah[r] = a; at[r] = t;
        }
#pragma unroll
        for (int off = 16; off; off >>= 1) {
#pragma unroll
            for (int r = 0; r < 4; r++) {
                ah[r] += __shfl_xor_sync(0xFFFFFFFFu, ah[r], off);
                at[r] += __shfl_xor_sync(0xFFFFFFFFu, at[r], off);
            }
        }
        if (lane == 0) {
#pragma unroll
            for (int r = 0; r < 4; r++) {
                g_dots[b * 2 * SZ + (r0 + r)]      = at[r];
                g_dots[b * 2 * SZ + SZ + (r0 + r)] = ah[r];
            }
        }
    }

    // ================= Election: 32nd arriving warp's block runs tail ====
    if (lane == 0) {
        __threadfence();
        unsigned old = atomicAdd(&g_tick[b], 1u);
        if (old == 31u) s_flag = 1;
    }
    __syncthreads();                                   // B2
    if (!s_flag) return;
    __threadfence();   // acquire side

    // ================= Tail (one block per batch) =========================
    if (tid == 0) { g_tick[b] = 0; s_len = 0; }
    if (tid < 4)            sbias[tid] = bi[tid];
    else if (tid < 8)       sbias[tid] = be[tid - 4];
    if (tid == 8) s_bh = bh_[0];
    if (tid == 9) s_bt = bt_[0];
    pref[tid >> 7][(tid & 127) + 1] = g_dots[b * 2 * SZ + tid];
    if (tid < 2) pref[tid][0] = 0.f;
    __syncthreads();                                   // B3

    // prefix (warps 0-1) in parallel with mask-length (warps 4-7)
    if (warp < 2) {
        const int c = warp;
        float v0 = pref[c][lane * 4 + 1];
        float v1 = pref[c][lane * 4 + 2];
        float v2 = pref[c][lane * 4 + 3];
        float v3 = pref[c][lane * 4 + 4];
        v1 += v0; v2 += v1; v3 += v2;
        float tot = v3, x = tot;
#pragma unroll
        for (int off = 1; off < 32; off <<= 1) {
            float y = __shfl_up_sync(0xFFFFFFFFu, x, off);
            if (lane >= off) x += y;
        }
        float excl = x - tot;
        pref[c][lane * 4 + 1] = v0 + excl;
        pref[c][lane * 4 + 2] = v1 + excl;
        pref[c][lane * 4 + 3] = v2 + excl;
        pref[c][lane * 4 + 4] = v3 + excl;
    } else if (warp >= 4) {
        int v = mask[b * SZ + (tid - 128)];
#pragma unroll
        for (int off = 16; off; off >>= 1) v += __shfl_xor_sync(0xFFFFFFFFu, v, off);
        if (lane == 0) atomicAdd(&s_len, v);
    }
    __syncthreads();                                   // B4

    // scores (4 spans/thread), write hs/ts, keep keys in registers
    unsigned long long kt[4], kh[4];
    {
        const int len = s_len;
        const float bhv = s_bh, btv = s_bt;
        float* out_hs = out + 2560  + (size_t)b * 1024;
        float* out_ts = out + 35328 + (size_t)b * 1024;
#pragma unroll
        for (int i = 0; i < 4; i++) {
            int idx = tid + 256 * i;
            int m = idx >> 7, s = idx & 127;
            int e = s + m + 1; if (e > SZ) e = SZ;
            float invw = c_inv[m];
            bool tv = (s + m) < len;
            bool hv = tv && (m < MH_);
            float dt = (pref[0][e] - pref[0][s]) * invw;
            float dh = (pref[1][e] - pref[1][s]) * invw;
            float vt = tv ? 1.f / (1.f + __expf(-(dt + btv))) : -1.f;
            float vh = hv ? 1.f / (1.f + __expf(-(dh + bhv))) : -1.f;
            out_ts[idx] = vt; out_hs[idx] = vh;
            unsigned ut = __float_as_uint(vt);
            unsigned uh = __float_as_uint(vh);
            ut = (ut & 0x80000000u) ? ~ut : (ut | 0x80000000u);
            uh = (uh & 0x80000000u) ? ~uh : (uh | 0x80000000u);
            kt[i] = ((unsigned long long)ut << 32) | (unsigned)(0xFFFFFFFFu - idx);
            kh[i] = ((unsigned long long)uh << 32) | (unsigned)(0xFFFFFFFFu - idx);
        }
    }
    // sort4 descending (5-CE network), both types interleaved for ILP
    CE(kt[0], kt[1]); CE(kh[0], kh[1]);
    CE(kt[2], kt[3]); CE(kh[2], kh[3]);
    CE(kt[0], kt[2]); CE(kh[0], kh[2]);
    CE(kt[1], kt[3]); CE(kh[1], kh[3]);
    CE(kt[1], kt[2]); CE(kh[1], kh[2]);

    // warp butterfly merge, t and h chains interleaved (independent latency)
#pragma unroll
    for (int off = 16; off; off >>= 1) {
        unsigned long long ot0 = __shfl_xor_sync(0xFFFFFFFFu, kt[0], off);
        unsigned long long oh0 = __shfl_xor_sync(0xFFFFFFFFu, kh[0], off);
        unsigned long long ot1 = __shfl_xor_sync(0xFFFFFFFFu, kt[1], off);
        unsigned long long oh1 = __shfl_xor_sync(0xFFFFFFFFu, kh[1], off);
        unsigned long long ot2 = __shfl_xor_sync(0xFFFFFFFFu, kt[2], off);
        unsigned long long oh2 = __shfl_xor_sync(0xFFFFFFFFu, kh[2], off);
        unsigned long long ot3 = __shfl_xor_sync(0xFFFFFFFFu, kt[3], off);
        unsigned long long oh3 = __shfl_xor_sync(0xFFFFFFFFu, kh[3], off);
        unsigned long long t0 = kt[0] > ot3 ? kt[0] : ot3;
        unsigned long long t1 = kt[1] > ot2 ? kt[1] : ot2;
        unsigned long long t2 = kt[2] > ot1 ? kt[2] : ot1;
        unsigned long long t3 = kt[3] > ot0 ? kt[3] : ot0;
        unsigned long long h0 = kh[0] > oh3 ? kh[0] : oh3;
        unsigned long long h1 = kh[1] > oh2 ? kh[1] : oh2;
        unsigned long long h2 = kh[2] > oh1 ? kh[2] : oh1;
        unsigned long long h3 = kh[3] > oh0 ? kh[3] : oh0;
        CE(t0, t2); CE(h0, h2);
        CE(t1, t3); CE(h1, h3);
        CE(t0, t1); CE(h0, h1);
        CE(t2, t3); CE(h2, h3);
        kt[0] = t0; kt[1] = t1; kt[2] = t2; kt[3] = t3;
        kh[0] = h0; kh[1] = h1; kh[2] = h2; kh[3] = h3;
    }
    if (lane == 0) {
#pragma unroll
        for (int j = 0; j < 4; j++) {
            candT[warp * 4 + j] = kt[j];
            candH[warp * 4 + j] = kh[j];
        }
    }
    __syncthreads();                                   // B5

    // final extraction: warp0 -> targets, warp1 -> holders (parallel)
    if (warp < 2) {
        const int type = warp;
        unsigned long long key = type ? candH[lane] : candT[lane];
#pragma unroll
        for (int k = 0; k < KK; k++) {
            unsigned long long red = key;
#pragma unroll
            for (int off = 16; off; off >>= 1) {
                unsigned long long o = __shfl_xor_sync(0xFFFFFFFFu, red, off);
                red = o > red ? o : red;
            }
            if (key == red) key = 0ull;
            if (lane == 0) {
                unsigned hi = (unsigned)(red >> 32);
                unsigned lo = (unsigned)red;
                float v = (hi & 0x80000000u) ? __uint_as_float(hi ^ 0x80000000u)
                                             : __uint_as_float(~hi);
                topv[type][k] = v;
                topi[type][k] = (int)(0xFFFFFFFFu - lo);
            }
        }
    }
    __syncthreads();                                   // B6

    // rep dots: 1 warp per selected span (warps 0-3 target, 4-7 holder),
    // weights straight from L2 (warm every replay)
    {
        const int type = warp >> 2;
        const int k = warp & 3;
        const int idx = topi[type][k];
        const bool valid = topv[type][k] > 0.f;
        const int m = idx >> 7, s = idx & 127;
        const float invw = c_inv[m];
        const float4* wi4 = (const float4*)wi;
        const float4* we4 = (const float4*)we;

        float acc[8] = {0.f,0.f,0.f,0.f,0.f,0.f,0.f,0.f};
        if (valid) {
            float4 sum[6];
#pragma unroll
            for (int i = 0; i < 6; i++) sum[i] = make_float4(0.f,0.f,0.f,0.f);
#pragma unroll
            for (int r = 0; r < 8; r++) {
                if (r <= m) {
                    const float4* rp = (const float4*)(eb + (size_t)(s + r) * HZ);
#pragma unroll
                    for (int i = 0; i < 6; i++) {
                        float4 a = rp[lane + 32 * i];
                        sum[i].x += a.x; sum[i].y += a.y;
                        sum[i].z += a.z; sum[i].w += a.w;
                    }
                }
            }
#pragma unroll
            for (int i = 0; i < 6; i++) {
                int h4 = lane + 32 * i;
                float sv[4] = {sum[i].x * invw, sum[i].y * invw,
                               sum[i].z * invw, sum[i].w * invw};
#pragma unroll
                for (int j = 0; j < 4; j++) {
                    int f = 4 * h4 + j;   // = h index
                    if (type == 0) {
                        float4 wv = wi4[f];
                        acc[0] += sv[j] * wv.x; acc[1] += sv[j] * wv.y;
                        acc[2] += sv[j] * wv.z; acc[3] += sv[j] * wv.w;
                        float4 ev = we4[HZ + f];
                        acc[4] += sv[j] * ev.x; acc[5] += sv[j] * ev.y;
                        acc[6] += sv[j] * ev.z; acc[7] += sv[j] * ev.w;
                    } else {
                        float4 ev = we4[f];
                        acc[0] += sv[j] * ev.x; acc[1] += sv[j] * ev.y;
                        acc[2] += sv[j] * ev.z; acc[3] += sv[j] * ev.w;
                    }
                }
            }
        }
#pragma unroll
        for (int off = 16; off; off >>= 1)
#pragma unroll
            for (int j = 0; j < 8; j++)
                acc[j] += __shfl_xor_sync(0xFFFFFFFFu, acc[j], off);
        if (lane == 0) {
#pragma unroll
            for (int j = 0; j < 8; j++) partial[warp][j] = acc[j];
        }
    }
    __syncthreads();                                   // B7

    // logits
    if (tid < 64) {
        int k = tid >> 4, i = (tid >> 2) & 3, j = tid & 3;
        bool pv = (topv[1][k] > 0.f) && (topv[0][i] > 0.f);
        float val = sbias[4 + j];
        if (pv) val += partial[4 + k][j] + partial[i][4 + j];
        out[512 + (size_t)b * 64 + tid] = val;
    } else if (tid < 80) {
        int t2 = tid - 64;
        int i = t2 >> 2, j = t2 & 3;
        float val = sbias[j];
        if (topv[0][i] > 0.f) val += partial[i][j];
        out[(size_t)b * 16 + t2] = val;
    }
}

extern "C" void kernel_launch(void* const* d_in, const int* in_sizes, int n_in,
                              void* d_out, int out_size)
{
    const float* emb = (const float*)d_in[0];
    const int*   msk = (const int*)d_in[1];
    const float* wh  = (const float*)d_in[2];
    const float* bh  = (const float*)d_in[3];
    const float* wt  = (const float*)d_in[4];
    const float* bt  = (const float*)d_in[5];
    const float* wi  = (const float*)d_in[6];
    const float* bi  = (const float*)d_in[7];
    const float* we  = (const float*)d_in[8];
    const float* be  = (const float*)d_in[9];
    float* out = (float*)d_out;

    dim3 g(BZ, 4, 1);
    k_all<<<g, 256>>>(emb, msk, wh, bh, wt, bt, wi, bi, we, be, out);
}